// round 6
// baseline (speedup 1.0000x reference)
#include <cuda_runtime.h>
#include <cuda_bf16.h>
#include <cuda_fp8.h>
#include <math.h>
#include <stdint.h>

#define BB 32
#define NN 2048
#define DD 256

#define L2_LAMDA 0.001f
#define RECONS_LAMDA 0.2f
#define LB_TH 0.01f

// Scale factors: products are exactly compensated (4 * 1/4)
#define SC_UP 4.0f
#define SC_DN 0.25f

// ---------------------------------------------------------------------------
// Device scratch (fp8 operands, all K-major for the GEMM)
// ---------------------------------------------------------------------------
__device__ uint8_t g_cur8[(size_t)BB * NN * DD];    // e4m3(cur/4)   [b][n][k]
__device__ uint8_t g_pre8T[(size_t)BB * DD * NN];   // e4m3(pre/4)   [b][d][m]
__device__ uint8_t g_w8[(size_t)NN * NN];           // e4m3(-4*W)    [n][m]
__device__ uint8_t g_r8T[DD * DD];                  // e4m3(4*R)     [j][k]
__device__ float g_rowterm[NN];
__device__ float g_part[2 * BB * NN];               // [dtile][b][n]

// ---------------------------------------------------------------------------
// PTX helpers
// ---------------------------------------------------------------------------
__device__ __forceinline__ uint32_t smem_u32(const void* p) {
    uint32_t a;
    asm("{ .reg .u64 t; cvta.to.shared.u64 t, %1; cvt.u32.u64 %0, t; }"
        : "=r"(a) : "l"(p));
    return a;
}

__device__ __forceinline__ void cp16(uint32_t dst, const void* src) {
    asm volatile("cp.async.cg.shared.global [%0], [%1], 16;"
                 :: "r"(dst), "l"(src) : "memory");
}
#define CP_COMMIT() asm volatile("cp.async.commit_group;" ::: "memory")

__device__ __forceinline__ void ldsm_x4(uint32_t& r0, uint32_t& r1,
                                        uint32_t& r2, uint32_t& r3, uint32_t addr) {
    asm volatile("ldmatrix.sync.aligned.m8n8.x4.shared.b16 {%0,%1,%2,%3}, [%4];"
                 : "=r"(r0), "=r"(r1), "=r"(r2), "=r"(r3) : "r"(addr));
}

__device__ __forceinline__ void mma16832(float* d, const uint32_t* a, const uint32_t* b) {
    asm volatile(
        "mma.sync.aligned.m16n8k32.row.col.f32.e4m3.e4m3.f32 "
        "{%0,%1,%2,%3}, {%4,%5,%6,%7}, {%8,%9}, {%0,%1,%2,%3};"
        : "+f"(d[0]), "+f"(d[1]), "+f"(d[2]), "+f"(d[3])
        : "r"(a[0]), "r"(a[1]), "r"(a[2]), "r"(a[3]), "r"(b[0]), "r"(b[1]));
}

// SW128 swizzle for 128B rows
#define SWZ(o) ((uint32_t)(o) ^ ((((uint32_t)(o)) >> 3) & 0x70))

__device__ __forceinline__ uint32_t pack_fp8x4(float a, float b, float c, float d) {
    unsigned short lo = __nv_cvt_float2_to_fp8x2(make_float2(a, b), __NV_SATFINITE, __NV_E4M3);
    unsigned short hi = __nv_cvt_float2_to_fp8x2(make_float2(c, d), __NV_SATFINITE, __NV_E4M3);
    return (uint32_t)lo | ((uint32_t)hi << 16);
}

// ---------------------------------------------------------------------------
// conv: cur -> e4m3(cur * SC_DN), same layout
// ---------------------------------------------------------------------------
__global__ __launch_bounds__(256) void conv_cur_kernel(const float4* __restrict__ src, int n4) {
    int i = blockIdx.x * blockDim.x + threadIdx.x;
    if (i >= n4) return;
    float4 v = src[i];
    ((uint32_t*)g_cur8)[i] = pack_fp8x4(v.x * SC_DN, v.y * SC_DN, v.z * SC_DN, v.w * SC_DN);
}

// Transpose fp32 [R][C] -> fp8 [C][R] with scale. which: 0 = g_pre8T, 1 = g_r8T
__global__ __launch_bounds__(256) void transpose_kernel(const float* __restrict__ src,
                                                        int which, int R, int C, float scale) {
    __shared__ float t[32][33];
    const int c0 = blockIdx.x * 32;
    const int r0 = blockIdx.y * 32;
    const float* s = src + (size_t)blockIdx.z * R * C;
    uint8_t* d = ((which == 0) ? g_pre8T : g_r8T) + (size_t)blockIdx.z * R * C;
    const int tx = threadIdx.x, ty = threadIdx.y;
#pragma unroll
    for (int i = 0; i < 4; i++)
        t[ty + i * 8][tx] = s[(size_t)(r0 + ty + i * 8) * C + c0 + tx];
    __syncthreads();
#pragma unroll
    for (int i = 0; i < 4; i++)
        d[(size_t)(c0 + ty + i * 8) * R + r0 + tx] =
            (uint8_t)__nv_cvt_float_to_fp8(t[tx][ty + i * 8] * scale, __NV_SATFINITE, __NV_E4M3);
}

// Masked incidence -> e4m3(-SC_UP * W) + per-row l1/l2 stats
__global__ __launch_bounds__(256) void conv_inc_kernel(const float* __restrict__ inc) {
    int n = blockIdx.x;
    int tid = threadIdx.x;
    const float4* row = (const float4*)(inc + (size_t)n * NN);
    uint32_t* wrow = (uint32_t*)(g_w8 + (size_t)n * NN);

    float mx = 0.0f, sq = 0.0f;
    for (int i = tid; i < NN / 4; i += 256) {
        float4 v = row[i];
        float a = (v.x > LB_TH) ? v.x : 0.0f;
        float b = (v.y > LB_TH) ? v.y : 0.0f;
        float c = (v.z > LB_TH) ? v.z : 0.0f;
        float d = (v.w > LB_TH) ? v.w : 0.0f;
        mx = fmaxf(mx, fmaxf(fmaxf(a, b), fmaxf(c, d)));
        sq += a * a + b * b + c * c + d * d;
        wrow[i] = pack_fp8x4(-SC_UP * a, -SC_UP * b, -SC_UP * c, -SC_UP * d);
    }

    __shared__ float smx[256];
    __shared__ float ssq[256];
    smx[tid] = mx; ssq[tid] = sq;
    __syncthreads();
    for (int s = 128; s > 0; s >>= 1) {
        if (tid < s) {
            smx[tid] = fmaxf(smx[tid], smx[tid + s]);
            ssq[tid] += ssq[tid + s];
        }
        __syncthreads();
    }
    if (tid == 0) g_rowterm[n] = smx[0] + L2_LAMDA * sqrtf(ssq[0]);
}

// ---------------------------------------------------------------------------
// Main GEMM (fp8): per CTA (dtile, ntile, b), 128(n) x 128(d) tile of
//   diff = (cur/4) @ (4R) + (-4W) @ (pre/4)     [exact-scale products]
// All operands K-major fp8, 128B rows (BK = 128 fp8), SW128 swizzle.
// 18 chunks: 2 (cur@R, K=256) + 16 (W@pre, K=2048). 3-stage cp.async pipeline.
// 8 warps: warp_m = w&3 (32 rows), warp_n = w>>2 (64 cols).
// ---------------------------------------------------------------------------
#define CHUNKS 18
#define STAGE_BYTES 32768    // 16KB A + 16KB B
#define NSTAGE 3
#define GEMM_SMEM (NSTAGE * STAGE_BYTES)   // 96KB; x2 CTAs = 192KB

__global__ __launch_bounds__(256, 2) void gemm_kernel() {
    extern __shared__ char smem[];
    const uint32_t sb = smem_u32(smem);
    const int tid = threadIdx.x;
    const int lane = tid & 31;
    const int w = tid >> 5;
    const int warp_m = w & 3;
    const int warp_n = w >> 2;

    const int dtile = blockIdx.x;           // 0..1
    const int ntile = blockIdx.y;           // 0..15
    const int b     = blockIdx.z;           // 0..31
    const int n0 = ntile * 128;
    const int d0 = dtile * 128;

    float acc[2][8][4];
#pragma unroll
    for (int mt = 0; mt < 2; mt++)
#pragma unroll
        for (int nt = 0; nt < 8; nt++)
#pragma unroll
            for (int i = 0; i < 4; i++) acc[mt][nt][i] = 0.0f;

    // per-lane ldsm bases: rows (lane&15), chunk-hi (lane>>4), swizzle (lane&7)
    uint32_t arow[2];
#pragma unroll
    for (int mt = 0; mt < 2; mt++)
        arow[mt] = (uint32_t)(warp_m * 32 + mt * 16 + (lane & 15)) * 128;
    uint32_t brow[4];
#pragma unroll
    for (int jg = 0; jg < 4; jg++)
        brow[jg] = (uint32_t)(warp_n * 64 + jg * 16 + (lane & 15)) * 128;
    const uint32_t alx = (lane & 7);
    const uint32_t ahi = (lane >> 4);

    const char* curb = (const char*)g_cur8 + ((size_t)b * NN + n0) * DD;
    const char* rtb  = (const char*)g_r8T + (size_t)d0 * DD;
    const char* wb   = (const char*)g_w8 + (size_t)n0 * NN;
    const char* ptb  = (const char*)g_pre8T + ((size_t)b * DD + d0) * NN;

    // 128 rows x 128B per tile: 1024 cp16 = 4 per thread
#define LOAD_KM(dst, src, ldbytes)                                              \
    _Pragma("unroll")                                                           \
    for (int i = 0; i < 4; i++) {                                               \
        int o = tid + i * 256;                                                  \
        int row = o >> 3, seg = o & 7;                                          \
        cp16((dst) + SWZ(row * 128 + seg * 16),                                 \
             (src) + (size_t)row * (ldbytes) + seg * 16);                       \
    }

#define LOAD_CHUNK(c)                                                           \
    {                                                                           \
        const uint32_t st = sb + ((c) % NSTAGE) * STAGE_BYTES;                  \
        if ((c) < 2) {                                                          \
            int k0 = (c) * 128;                                                 \
            LOAD_KM(st, curb + k0, DD);                                         \
            LOAD_KM(st + 16384, rtb + k0, DD);                                  \
        } else {                                                                \
            int k0 = ((c) - 2) * 128;                                           \
            LOAD_KM(st, wb + k0, NN);                                           \
            LOAD_KM(st + 16384, ptb + k0, NN);                                  \
        }                                                                       \
        CP_COMMIT();                                                            \
    }

    LOAD_CHUNK(0);
    LOAD_CHUNK(1);

    for (int c = 0; c < CHUNKS; c++) {
        if (c + 1 < CHUNKS)
            asm volatile("cp.async.wait_group 1;" ::: "memory");
        else
            asm volatile("cp.async.wait_group 0;" ::: "memory");
        __syncthreads();

        if (c + 2 < CHUNKS) LOAD_CHUNK(c + 2);

        const uint32_t sA = sb + (c % NSTAGE) * STAGE_BYTES;
        const uint32_t sB = sA + 16384;

#pragma unroll
        for (int s = 0; s < 4; s++) {           // 4 ksteps of k32 (32B each)
            const uint32_t ch = (uint32_t)(s * 2) + ahi;
            const uint32_t csw = (ch ^ alx) << 4;
            uint32_t a[2][4];
#pragma unroll
            for (int mt = 0; mt < 2; mt++)
                ldsm_x4(a[mt][0], a[mt][1], a[mt][2], a[mt][3],
                        sA + arow[mt] + csw);
            uint32_t bf[8][2];
#pragma unroll
            for (int jg = 0; jg < 4; jg++)
                ldsm_x4(bf[2 * jg][0], bf[2 * jg + 1][0],
                        bf[2 * jg][1], bf[2 * jg + 1][1],
                        sB + brow[jg] + csw);
#pragma unroll
            for (int mt = 0; mt < 2; mt++)
#pragma unroll
                for (int nt = 0; nt < 8; nt++)
                    mma16832(acc[mt][nt], a[mt], bf[nt]);
        }
    }

    // ------------- epilogue: per-row sum of squares -------------
    __shared__ float red[128][2];
#pragma unroll
    for (int mt = 0; mt < 2; mt++) {
        float s0 = 0.0f, s1 = 0.0f;
#pragma unroll
        for (int nt = 0; nt < 8; nt++) {
            s0 = fmaf(acc[mt][nt][0], acc[mt][nt][0], s0);
            s0 = fmaf(acc[mt][nt][1], acc[mt][nt][1], s0);
            s1 = fmaf(acc[mt][nt][2], acc[mt][nt][2], s1);
            s1 = fmaf(acc[mt][nt][3], acc[mt][nt][3], s1);
        }
        s0 += __shfl_xor_sync(0xFFFFFFFF, s0, 1);
        s0 += __shfl_xor_sync(0xFFFFFFFF, s0, 2);
        s1 += __shfl_xor_sync(0xFFFFFFFF, s1, 1);
        s1 += __shfl_xor_sync(0xFFFFFFFF, s1, 2);
        if ((lane & 3) == 0) {
            int r = warp_m * 32 + mt * 16 + (lane >> 2);
            red[r][warp_n] = s0;
            red[r + 8][warp_n] = s1;
        }
    }
    __syncthreads();
    if (tid < 128) {
        float t = red[tid][0] + red[tid][1];
        g_part[((size_t)dtile * BB + b) * NN + n0 + tid] = t;
    }
}

// ---------------------------------------------------------------------------
// Finalize: out[b] = 0.2 * sum_n sqrt(part0 + part1) + sum_n rowterm
// ---------------------------------------------------------------------------
__global__ __launch_bounds__(256) void finalize_kernel(float* __restrict__ out) {
    int b = blockIdx.x;
    int tid = threadIdx.x;
    float srec = 0.0f, srow = 0.0f;
    for (int n = tid; n < NN; n += 256) {
        float t = g_part[((size_t)0 * BB + b) * NN + n]
                + g_part[((size_t)1 * BB + b) * NN + n];
        srec += sqrtf(t);
        srow += g_rowterm[n];
    }
    __shared__ float s1[256];
    __shared__ float s2[256];
    s1[tid] = srec; s2[tid] = srow;
    __syncthreads();
    for (int s = 128; s > 0; s >>= 1) {
        if (tid < s) { s1[tid] += s1[tid + s]; s2[tid] += s2[tid + s]; }
        __syncthreads();
    }
    if (tid == 0) out[b] = RECONS_LAMDA * s1[0] + s2[0];
}

// ---------------------------------------------------------------------------
extern "C" void kernel_launch(void* const* d_in, const int* in_sizes, int n_in,
                              void* d_out, int out_size) {
    const float* cur = nullptr;
    const float* pre = nullptr;
    const float* rproj = nullptr;
    const float* inc = nullptr;
    int big_seen = 0;
    for (int i = 0; i < n_in; i++) {
        if (in_sizes[i] == DD * DD) rproj = (const float*)d_in[i];
        else if (in_sizes[i] == NN * NN) inc = (const float*)d_in[i];
        else if (in_sizes[i] == BB * NN * DD) {
            if (big_seen == 0) cur = (const float*)d_in[i];
            else pre = (const float*)d_in[i];
            big_seen++;
        }
    }
    float* out = (float*)d_out;

    cudaFuncSetAttribute(gemm_kernel, cudaFuncAttributeMaxDynamicSharedMemorySize, GEMM_SMEM);

    const int n4_big = BB * NN * DD / 4;
    conv_cur_kernel<<<n4_big / 256, 256>>>((const float4*)cur, n4_big);
    transpose_kernel<<<dim3(DD / 32, NN / 32, BB), dim3(32, 8)>>>(pre, 0, NN, DD, SC_DN);
    transpose_kernel<<<dim3(DD / 32, DD / 32, 1), dim3(32, 8)>>>(rproj, 1, DD, DD, SC_UP);
    conv_inc_kernel<<<NN, 256>>>(inc);

    gemm_kernel<<<dim3(2, 16, BB), 256, GEMM_SMEM>>>();
    finalize_kernel<<<BB, 256>>>(out);

    if (out_size >= BB + NN * NN) {
        cudaMemcpyAsync(out + BB, inc, (size_t)NN * NN * sizeof(float),
                        cudaMemcpyDeviceToDevice, 0);
    }
}

// round 7
// speedup vs baseline: 1.1106x; 1.1106x over previous
#include <cuda_runtime.h>
#include <cuda_bf16.h>
#include <math.h>
#include <stdint.h>

#define BB 32
#define NN 2048
#define DD 256

#define L2_LAMDA 0.001f
#define RECONS_LAMDA 0.2f
#define LB_TH 0.01f

// ---------------------------------------------------------------------------
// Device scratch
// ---------------------------------------------------------------------------
__device__ __nv_bfloat16 g_cur_bf[(size_t)BB * NN * DD];   // [b][n][k]
__device__ __nv_bfloat16 g_pre_bf[(size_t)BB * NN * DD];   // [b][m][d]  (natural)
__device__ __nv_bfloat16 g_w_bf[(size_t)NN * NN];          // NEGATED masked incidence [n][m]
__device__ __nv_bfloat16 g_r_bf[DD * DD];                  // [k][j]     (natural)
__device__ float g_rowterm[NN];
__device__ float g_part[2 * BB * NN];                      // [dtile][b][n]

// ---------------------------------------------------------------------------
// PTX helpers
// ---------------------------------------------------------------------------
__device__ __forceinline__ uint32_t smem_u32(const void* p) {
    uint32_t a;
    asm("{ .reg .u64 t; cvta.to.shared.u64 t, %1; cvt.u32.u64 %0, t; }"
        : "=r"(a) : "l"(p));
    return a;
}

__device__ __forceinline__ void cp16(uint32_t dst, const void* src) {
    asm volatile("cp.async.cg.shared.global [%0], [%1], 16;"
                 :: "r"(dst), "l"(src) : "memory");
}
#define CP_COMMIT() asm volatile("cp.async.commit_group;" ::: "memory")

__device__ __forceinline__ void ldsm_x4(uint32_t& r0, uint32_t& r1,
                                        uint32_t& r2, uint32_t& r3, uint32_t addr) {
    asm volatile("ldmatrix.sync.aligned.m8n8.x4.shared.b16 {%0,%1,%2,%3}, [%4];"
                 : "=r"(r0), "=r"(r1), "=r"(r2), "=r"(r3) : "r"(addr));
}
__device__ __forceinline__ void ldsm_x4t(uint32_t& r0, uint32_t& r1,
                                         uint32_t& r2, uint32_t& r3, uint32_t addr) {
    asm volatile("ldmatrix.sync.aligned.m8n8.x4.trans.shared.b16 {%0,%1,%2,%3}, [%4];"
                 : "=r"(r0), "=r"(r1), "=r"(r2), "=r"(r3) : "r"(addr));
}

__device__ __forceinline__ void mma16816(float* d, const uint32_t* a, const uint32_t* b) {
    asm volatile(
        "mma.sync.aligned.m16n8k16.row.col.f32.bf16.bf16.f32 "
        "{%0,%1,%2,%3}, {%4,%5,%6,%7}, {%8,%9}, {%0,%1,%2,%3};"
        : "+f"(d[0]), "+f"(d[1]), "+f"(d[2]), "+f"(d[3])
        : "r"(a[0]), "r"(a[1]), "r"(a[2]), "r"(a[3]), "r"(b[0]), "r"(b[1]));
}

// SW128 swizzle for 128B rows
#define SWZ(o) ((uint32_t)(o) ^ ((((uint32_t)(o)) >> 3) & 0x70))

// ---------------------------------------------------------------------------
// Merged conversion: cur AND pre -> bf16 in one launch (blockIdx.y selects)
// ---------------------------------------------------------------------------
__global__ __launch_bounds__(256) void conv_big_kernel(const float4* __restrict__ cur,
                                                       const float4* __restrict__ pre,
                                                       int n4) {
    int i = blockIdx.x * blockDim.x + threadIdx.x;
    if (i >= n4) return;
    const float4* src = blockIdx.y ? pre : cur;
    __nv_bfloat162* dst = blockIdx.y ? (__nv_bfloat162*)g_pre_bf
                                     : (__nv_bfloat162*)g_cur_bf;
    float4 v = src[i];
    dst[2 * i]     = __floats2bfloat162_rn(v.x, v.y);
    dst[2 * i + 1] = __floats2bfloat162_rn(v.z, v.w);
}

__global__ __launch_bounds__(256) void conv_r_kernel(const float4* __restrict__ src, int n4) {
    int i = blockIdx.x * blockDim.x + threadIdx.x;
    if (i >= n4) return;
    __nv_bfloat162* dst = (__nv_bfloat162*)g_r_bf;
    float4 v = src[i];
    dst[2 * i]     = __floats2bfloat162_rn(v.x, v.y);
    dst[2 * i + 1] = __floats2bfloat162_rn(v.z, v.w);
}

// Masked+negated bf16 incidence + per-row l1/l2 stats
__global__ __launch_bounds__(256) void conv_inc_kernel(const float* __restrict__ inc) {
    int n = blockIdx.x;
    int tid = threadIdx.x;
    const float4* row = (const float4*)(inc + (size_t)n * NN);
    __nv_bfloat162* wrow = (__nv_bfloat162*)(g_w_bf + (size_t)n * NN);

    float mx = 0.0f, sq = 0.0f;
    for (int i = tid; i < NN / 4; i += 256) {
        float4 v = row[i];
        float a = (v.x > LB_TH) ? v.x : 0.0f;
        float b = (v.y > LB_TH) ? v.y : 0.0f;
        float c = (v.z > LB_TH) ? v.z : 0.0f;
        float d = (v.w > LB_TH) ? v.w : 0.0f;
        mx = fmaxf(mx, fmaxf(fmaxf(a, b), fmaxf(c, d)));
        sq += a * a + b * b + c * c + d * d;
        wrow[2 * i]     = __floats2bfloat162_rn(-a, -b);
        wrow[2 * i + 1] = __floats2bfloat162_rn(-c, -d);
    }

    __shared__ float smx[256];
    __shared__ float ssq[256];
    smx[tid] = mx; ssq[tid] = sq;
    __syncthreads();
    for (int s = 128; s > 0; s >>= 1) {
        if (tid < s) {
            smx[tid] = fmaxf(smx[tid], smx[tid + s]);
            ssq[tid] += ssq[tid + s];
        }
        __syncthreads();
    }
    if (tid == 0) g_rowterm[n] = smx[0] + L2_LAMDA * sqrtf(ssq[0]);
}

// ---------------------------------------------------------------------------
// Main GEMM (identical mainloop to the proven 238us round-5 kernel):
// per CTA (dtile, ntile, b): 128x128 tile of diff = cur_b @ R + (-W) @ pre_b
// A smem: [128 rows][64 k] K-major, 128B rows, SW128.
// B smem: [64 k][128 j] trans layout, 256B rows, chunk ^= (krow & 7).
// 3-stage cp.async pipeline, ONE __syncthreads per chunk.
// ---------------------------------------------------------------------------
#define CHUNKS 36            // 4 (cur@R, K=256) + 32 (W@pre, K=2048)
#define STAGE_BYTES 32768    // 16KB A + 16KB B
#define NSTAGE 3
#define GEMM_SMEM (NSTAGE * STAGE_BYTES)   // 98304; x2 CTAs = 192KB

__global__ __launch_bounds__(256, 2) void gemm_kernel() {
    extern __shared__ char smem[];
    const uint32_t sb = smem_u32(smem);
    const int tid = threadIdx.x;
    const int lane = tid & 31;
    const int w = tid >> 5;
    const int warp_m = w & 3;
    const int warp_n = w >> 2;

    const int dtile = blockIdx.x;           // 0..1
    const int ntile = blockIdx.y;           // 0..15
    const int b     = blockIdx.z;           // 0..31
    const int n0 = ntile * 128;
    const int d0 = dtile * 128;

    float acc[2][8][4];
#pragma unroll
    for (int mt = 0; mt < 2; mt++)
#pragma unroll
        for (int nt = 0; nt < 8; nt++)
#pragma unroll
            for (int i = 0; i < 4; i++) acc[mt][nt][i] = 0.0f;

    uint32_t arow[2];
#pragma unroll
    for (int mt = 0; mt < 2; mt++)
        arow[mt] = (uint32_t)(warp_m * 32 + mt * 16 + (lane & 15)) * 128;
    const uint32_t alx = (lane & 7);
    const uint32_t ahi = (lane >> 4);
    uint32_t btb[4];
#pragma unroll
    for (int jg = 0; jg < 4; jg++) {
        uint32_t cb = (uint32_t)(warp_n * 8 + jg * 2) + (lane >> 4);
        btb[jg] = (uint32_t)(lane & 15) * 256 + ((cb ^ (lane & 7)) << 4);
    }

    const __nv_bfloat16* curb = g_cur_bf + ((size_t)b * NN + n0) * DD;
    const __nv_bfloat16* preb = g_pre_bf + (size_t)b * NN * DD + d0;
    const __nv_bfloat16* wb   = g_w_bf + (size_t)n0 * NN;
    const __nv_bfloat16* rb   = g_r_bf + d0;

#define LOAD_KM(dst, src, ld)                                                   \
    _Pragma("unroll")                                                           \
    for (int i = 0; i < 4; i++) {                                               \
        int o = tid + i * 256;                                                  \
        int row = o >> 3, seg = o & 7;                                          \
        cp16((dst) + SWZ(row * 128 + seg * 16),                                 \
             (src) + (size_t)row * (ld) + seg * 8);                             \
    }
#define LOAD_TR(dst, src, ld)                                                   \
    _Pragma("unroll")                                                           \
    for (int i = 0; i < 4; i++) {                                               \
        int o = tid + i * 256;                                                  \
        int row = o >> 4, seg = o & 15;                                         \
        cp16((dst) + row * 256 + (((seg ^ (row & 7))) << 4),                    \
             (src) + (size_t)row * (ld) + seg * 8);                             \
    }

#define LOAD_CHUNK(c)                                                           \
    {                                                                           \
        const uint32_t st = sb + ((c) % NSTAGE) * STAGE_BYTES;                  \
        if ((c) < 4) {                                                          \
            int k0 = (c) * 64;                                                  \
            LOAD_KM(st, curb + k0, DD);                                         \
            LOAD_TR(st + 16384, rb + (size_t)k0 * DD, DD);                      \
        } else {                                                                \
            int k0 = ((c) - 4) * 64;                                            \
            LOAD_KM(st, wb + k0, NN);                                           \
            LOAD_TR(st + 16384, preb + (size_t)k0 * DD, DD);                    \
        }                                                                       \
        CP_COMMIT();                                                            \
    }

    LOAD_CHUNK(0);
    LOAD_CHUNK(1);

    for (int c = 0; c < CHUNKS; c++) {
        if (c + 1 < CHUNKS)
            asm volatile("cp.async.wait_group 1;" ::: "memory");
        else
            asm volatile("cp.async.wait_group 0;" ::: "memory");
        __syncthreads();

        if (c + 2 < CHUNKS) LOAD_CHUNK(c + 2);

        const uint32_t sA = sb + (c % NSTAGE) * STAGE_BYTES;
        const uint32_t sB = sA + 16384;

#pragma unroll
        for (int s = 0; s < 4; s++) {
            uint32_t a[2][4];
#pragma unroll
            for (int mt = 0; mt < 2; mt++) {
                uint32_t ch = (uint32_t)(s * 2) + ahi;
                ldsm_x4(a[mt][0], a[mt][1], a[mt][2], a[mt][3],
                        sA + arow[mt] + ((ch ^ alx) << 4));
            }
            uint32_t bf[8][2];
#pragma unroll
            for (int jg = 0; jg < 4; jg++)
                ldsm_x4t(bf[2 * jg][0], bf[2 * jg][1],
                         bf[2 * jg + 1][0], bf[2 * jg + 1][1],
                         sB + s * 4096 + btb[jg]);
#pragma unroll
            for (int mt = 0; mt < 2; mt++)
#pragma unroll
                for (int nt = 0; nt < 8; nt++)
                    mma16816(acc[mt][nt], a[mt], bf[nt]);
        }
    }

    // ------------- epilogue: per-row sum of squares -------------
    __shared__ float red[128][2];
#pragma unroll
    for (int mt = 0; mt < 2; mt++) {
        float s0 = 0.0f, s1 = 0.0f;
#pragma unroll
        for (int nt = 0; nt < 8; nt++) {
            s0 = fmaf(acc[mt][nt][0], acc[mt][nt][0], s0);
            s0 = fmaf(acc[mt][nt][1], acc[mt][nt][1], s0);
            s1 = fmaf(acc[mt][nt][2], acc[mt][nt][2], s1);
            s1 = fmaf(acc[mt][nt][3], acc[mt][nt][3], s1);
        }
        s0 += __shfl_xor_sync(0xFFFFFFFF, s0, 1);
        s0 += __shfl_xor_sync(0xFFFFFFFF, s0, 2);
        s1 += __shfl_xor_sync(0xFFFFFFFF, s1, 1);
        s1 += __shfl_xor_sync(0xFFFFFFFF, s1, 2);
        if ((lane & 3) == 0) {
            int r = warp_m * 32 + mt * 16 + (lane >> 2);
            red[r][warp_n] = s0;
            red[r + 8][warp_n] = s1;
        }
    }
    __syncthreads();
    if (tid < 128) {
        float t = red[tid][0] + red[tid][1];
        g_part[((size_t)dtile * BB + b) * NN + n0 + tid] = t;
    }
}

// ---------------------------------------------------------------------------
// Finalize: out[b] = 0.2 * sum_n sqrt(part0 + part1) + sum_n rowterm
// ---------------------------------------------------------------------------
__global__ __launch_bounds__(256) void finalize_kernel(float* __restrict__ out) {
    int b = blockIdx.x;
    int tid = threadIdx.x;
    float srec = 0.0f, srow = 0.0f;
    for (int n = tid; n < NN; n += 256) {
        float t = g_part[((size_t)0 * BB + b) * NN + n]
                + g_part[((size_t)1 * BB + b) * NN + n];
        srec += sqrtf(t);
        srow += g_rowterm[n];
    }
    __shared__ float s1[256];
    __shared__ float s2[256];
    s1[tid] = srec; s2[tid] = srow;
    __syncthreads();
    for (int s = 128; s > 0; s >>= 1) {
        if (tid < s) { s1[tid] += s1[tid + s]; s2[tid] += s2[tid + s]; }
        __syncthreads();
    }
    if (tid == 0) out[b] = RECONS_LAMDA * s1[0] + s2[0];
}

// ---------------------------------------------------------------------------
extern "C" void kernel_launch(void* const* d_in, const int* in_sizes, int n_in,
                              void* d_out, int out_size) {
    const float* cur = nullptr;
    const float* pre = nullptr;
    const float* rproj = nullptr;
    const float* inc = nullptr;
    int big_seen = 0;
    for (int i = 0; i < n_in; i++) {
        if (in_sizes[i] == DD * DD) rproj = (const float*)d_in[i];
        else if (in_sizes[i] == NN * NN) inc = (const float*)d_in[i];
        else if (in_sizes[i] == BB * NN * DD) {
            if (big_seen == 0) cur = (const float*)d_in[i];
            else pre = (const float*)d_in[i];
            big_seen++;
        }
    }
    float* out = (float*)d_out;

    cudaFuncSetAttribute(gemm_kernel, cudaFuncAttributeMaxDynamicSharedMemorySize, GEMM_SMEM);

    const int n4_big = BB * NN * DD / 4;
    // Launch order places gemm_kernel in the ncu capture slot (4th launch).
    conv_inc_kernel<<<NN, 256>>>(inc);                                        // 1
    conv_r_kernel<<<DD * DD / 4 / 256, 256>>>((const float4*)rproj, DD * DD / 4); // 2
    conv_big_kernel<<<dim3(n4_big / 256, 2), 256>>>((const float4*)cur,
                                                    (const float4*)pre, n4_big); // 3
    gemm_kernel<<<dim3(2, 16, BB), 256, GEMM_SMEM>>>();                       // 4
    finalize_kernel<<<BB, 256>>>(out);                                        // 5

    if (out_size >= BB + NN * NN) {
        cudaMemcpyAsync(out + BB, inc, (size_t)NN * NN * sizeof(float),
                        cudaMemcpyDeviceToDevice, 0);
    }
}

// round 8
// speedup vs baseline: 1.1393x; 1.0258x over previous
#include <cuda_runtime.h>
#include <cuda_bf16.h>
#include <math.h>
#include <stdint.h>

#define BB 32
#define NN 2048
#define DD 256

#define L2_LAMDA 0.001f
#define RECONS_LAMDA 0.2f
#define LB_TH 0.01f

// ---------------------------------------------------------------------------
// Device scratch
// ---------------------------------------------------------------------------
__device__ __nv_bfloat16 g_cur_bf[(size_t)BB * NN * DD];   // [b][n][k]
__device__ __nv_bfloat16 g_pre_bf[(size_t)BB * NN * DD];   // [b][m][d]  (natural)
__device__ __nv_bfloat16 g_w_bf[(size_t)NN * NN];          // NEGATED masked incidence [n][m]
__device__ __nv_bfloat16 g_r_bf[DD * DD];                  // [k][j]     (natural)
__device__ float g_rowterm[NN];
__device__ float g_part[2 * BB * NN];                      // [dtile][b][n]

// ---------------------------------------------------------------------------
// PTX helpers
// ---------------------------------------------------------------------------
__device__ __forceinline__ uint32_t smem_u32(const void* p) {
    uint32_t a;
    asm("{ .reg .u64 t; cvta.to.shared.u64 t, %1; cvt.u32.u64 %0, t; }"
        : "=r"(a) : "l"(p));
    return a;
}

__device__ __forceinline__ void cp16(uint32_t dst, const void* src) {
    asm volatile("cp.async.cg.shared.global [%0], [%1], 16;"
                 :: "r"(dst), "l"(src) : "memory");
}
#define CP_COMMIT() asm volatile("cp.async.commit_group;" ::: "memory")

__device__ __forceinline__ void ldsm_x4(uint32_t& r0, uint32_t& r1,
                                        uint32_t& r2, uint32_t& r3, uint32_t addr) {
    asm volatile("ldmatrix.sync.aligned.m8n8.x4.shared.b16 {%0,%1,%2,%3}, [%4];"
                 : "=r"(r0), "=r"(r1), "=r"(r2), "=r"(r3) : "r"(addr));
}
__device__ __forceinline__ void ldsm_x4t(uint32_t& r0, uint32_t& r1,
                                         uint32_t& r2, uint32_t& r3, uint32_t addr) {
    asm volatile("ldmatrix.sync.aligned.m8n8.x4.trans.shared.b16 {%0,%1,%2,%3}, [%4];"
                 : "=r"(r0), "=r"(r1), "=r"(r2), "=r"(r3) : "r"(addr));
}

__device__ __forceinline__ void mma16816(float* d, const uint32_t* a, const uint32_t* b) {
    asm volatile(
        "mma.sync.aligned.m16n8k16.row.col.f32.bf16.bf16.f32 "
        "{%0,%1,%2,%3}, {%4,%5,%6,%7}, {%8,%9}, {%0,%1,%2,%3};"
        : "+f"(d[0]), "+f"(d[1]), "+f"(d[2]), "+f"(d[3])
        : "r"(a[0]), "r"(a[1]), "r"(a[2]), "r"(a[3]), "r"(b[0]), "r"(b[1]));
}

// SW128 swizzle for 128B rows
#define SWZ(o) ((uint32_t)(o) ^ ((((uint32_t)(o)) >> 3) & 0x70))

// ---------------------------------------------------------------------------
// Merged conversion: cur AND pre -> bf16 in one launch (blockIdx.y selects)
// ---------------------------------------------------------------------------
__global__ __launch_bounds__(256) void conv_big_kernel(const float4* __restrict__ cur,
                                                       const float4* __restrict__ pre,
                                                       int n4) {
    int i = blockIdx.x * blockDim.x + threadIdx.x;
    if (i >= n4) return;
    const float4* src = blockIdx.y ? pre : cur;
    __nv_bfloat162* dst = blockIdx.y ? (__nv_bfloat162*)g_pre_bf
                                     : (__nv_bfloat162*)g_cur_bf;
    float4 v = src[i];
    dst[2 * i]     = __floats2bfloat162_rn(v.x, v.y);
    dst[2 * i + 1] = __floats2bfloat162_rn(v.z, v.w);
}

__global__ __launch_bounds__(256) void conv_r_kernel(const float4* __restrict__ src, int n4) {
    int i = blockIdx.x * blockDim.x + threadIdx.x;
    if (i >= n4) return;
    __nv_bfloat162* dst = (__nv_bfloat162*)g_r_bf;
    float4 v = src[i];
    dst[2 * i]     = __floats2bfloat162_rn(v.x, v.y);
    dst[2 * i + 1] = __floats2bfloat162_rn(v.z, v.w);
}

// Masked+negated bf16 incidence + per-row l1/l2 stats
__global__ __launch_bounds__(256) void conv_inc_kernel(const float* __restrict__ inc) {
    int n = blockIdx.x;
    int tid = threadIdx.x;
    const float4* row = (const float4*)(inc + (size_t)n * NN);
    __nv_bfloat162* wrow = (__nv_bfloat162*)(g_w_bf + (size_t)n * NN);

    float mx = 0.0f, sq = 0.0f;
    for (int i = tid; i < NN / 4; i += 256) {
        float4 v = row[i];
        float a = (v.x > LB_TH) ? v.x : 0.0f;
        float b = (v.y > LB_TH) ? v.y : 0.0f;
        float c = (v.z > LB_TH) ? v.z : 0.0f;
        float d = (v.w > LB_TH) ? v.w : 0.0f;
        mx = fmaxf(mx, fmaxf(fmaxf(a, b), fmaxf(c, d)));
        sq += a * a + b * b + c * c + d * d;
        wrow[2 * i]     = __floats2bfloat162_rn(-a, -b);
        wrow[2 * i + 1] = __floats2bfloat162_rn(-c, -d);
    }

    __shared__ float smx[256];
    __shared__ float ssq[256];
    smx[tid] = mx; ssq[tid] = sq;
    __syncthreads();
    for (int s = 128; s > 0; s >>= 1) {
        if (tid < s) {
            smx[tid] = fmaxf(smx[tid], smx[tid + s]);
            ssq[tid] += ssq[tid + s];
        }
        __syncthreads();
    }
    if (tid == 0) g_rowterm[n] = smx[0] + L2_LAMDA * sqrtf(ssq[0]);
}

// ---------------------------------------------------------------------------
// Main GEMM: per CTA (dtile, ntile, b) compute 128x128 tile of
//   diff = cur_b @ R + (-W) @ pre_b   (fp32 reg accum, bf16 HMMA)
// NEW: 4 warps, each 64(rows) x 64(cols) -> SMEM reads drop 96KB->64KB/chunk.
// A smem: [128 rows][64 k] K-major, 128B rows, SW128.
// B smem: [64 k][128 j] trans layout, 256B rows, chunk ^= (krow & 7).
// 3-stage cp.async pipeline, ONE __syncthreads per chunk.
// warp_m = w&1 (64 rows), warp_n = w>>1 (64 cols).
// ---------------------------------------------------------------------------
#define CHUNKS 36            // 4 (cur@R, K=256) + 32 (W@pre, K=2048)
#define STAGE_BYTES 32768    // 16KB A + 16KB B
#define NSTAGE 3
#define GEMM_SMEM (NSTAGE * STAGE_BYTES)   // 98304; x2 CTAs = 192KB

__global__ __launch_bounds__(128, 2) void gemm_kernel() {
    extern __shared__ char smem[];
    const uint32_t sb = smem_u32(smem);
    const int tid = threadIdx.x;
    const int lane = tid & 31;
    const int w = tid >> 5;          // 0..3
    const int warp_m = w & 1;        // 64-row half
    const int warp_n = w >> 1;       // 64-col half

    const int dtile = blockIdx.x;    // 0..1
    const int ntile = blockIdx.y;    // 0..15
    const int b     = blockIdx.z;    // 0..31
    const int n0 = ntile * 128;
    const int d0 = dtile * 128;

    float acc[4][8][4];
#pragma unroll
    for (int mt = 0; mt < 4; mt++)
#pragma unroll
        for (int nt = 0; nt < 8; nt++)
#pragma unroll
            for (int i = 0; i < 4; i++) acc[mt][nt][i] = 0.0f;

    // A fragment addresses: rows warp_m*64 + mt*16 + (lane&15), 128B rows
    uint32_t arow[4];
#pragma unroll
    for (int mt = 0; mt < 4; mt++)
        arow[mt] = (uint32_t)(warp_m * 64 + mt * 16 + (lane & 15)) * 128;
    const uint32_t alx = (lane & 7);
    const uint32_t ahi = (lane >> 4);
    // B (trans) fragment addresses: 256B k-rows, chunk = warp_n*8 + jg*2 + (lane>>4)
    uint32_t btb[4];
#pragma unroll
    for (int jg = 0; jg < 4; jg++) {
        uint32_t cb = (uint32_t)(warp_n * 8 + jg * 2) + (lane >> 4);
        btb[jg] = (uint32_t)(lane & 15) * 256 + ((cb ^ (lane & 7)) << 4);
    }

    const __nv_bfloat16* curb = g_cur_bf + ((size_t)b * NN + n0) * DD;
    const __nv_bfloat16* preb = g_pre_bf + (size_t)b * NN * DD + d0;
    const __nv_bfloat16* wb   = g_w_bf + (size_t)n0 * NN;
    const __nv_bfloat16* rb   = g_r_bf + d0;

    // 128 threads: A tile (128x128B) = 1024 cp16 -> 8/thread; B same.
#define LOAD_KM(dst, src, ld)                                                   \
    _Pragma("unroll")                                                           \
    for (int i = 0; i < 8; i++) {                                               \
        int o = tid + i * 128;                                                  \
        int row = o >> 3, seg = o & 7;                                          \
        cp16((dst) + SWZ(row * 128 + seg * 16),                                 \
             (src) + (size_t)row * (ld) + seg * 8);                             \
    }
#define LOAD_TR(dst, src, ld)                                                   \
    _Pragma("unroll")                                                           \
    for (int i = 0; i < 8; i++) {                                               \
        int o = tid + i * 128;                                                  \
        int row = o >> 4, seg = o & 15;                                         \
        cp16((dst) + row * 256 + (((seg ^ (row & 7))) << 4),                    \
             (src) + (size_t)row * (ld) + seg * 8);                             \
    }

#define LOAD_CHUNK(c)                                                           \
    {                                                                           \
        const uint32_t st = sb + ((c) % NSTAGE) * STAGE_BYTES;                  \
        if ((c) < 4) {                                                          \
            int k0 = (c) * 64;                                                  \
            LOAD_KM(st, curb + k0, DD);                                         \
            LOAD_TR(st + 16384, rb + (size_t)k0 * DD, DD);                      \
        } else {                                                                \
            int k0 = ((c) - 4) * 64;                                            \
            LOAD_KM(st, wb + k0, NN);                                           \
            LOAD_TR(st + 16384, preb + (size_t)k0 * DD, DD);                    \
        }                                                                       \
        CP_COMMIT();                                                            \
    }

    LOAD_CHUNK(0);
    LOAD_CHUNK(1);

    for (int c = 0; c < CHUNKS; c++) {
        if (c + 1 < CHUNKS)
            asm volatile("cp.async.wait_group 1;" ::: "memory");
        else
            asm volatile("cp.async.wait_group 0;" ::: "memory");
        __syncthreads();

        if (c + 2 < CHUNKS) LOAD_CHUNK(c + 2);

        const uint32_t sA = sb + (c % NSTAGE) * STAGE_BYTES;
        const uint32_t sB = sA + 16384;

#pragma unroll
        for (int s = 0; s < 4; s++) {
            const uint32_t ch = (uint32_t)(s * 2) + ahi;
            const uint32_t csw = (ch ^ alx) << 4;
            uint32_t a[4][4];
#pragma unroll
            for (int mt = 0; mt < 4; mt++)
                ldsm_x4(a[mt][0], a[mt][1], a[mt][2], a[mt][3],
                        sA + arow[mt] + csw);
            uint32_t bf[8][2];
#pragma unroll
            for (int jg = 0; jg < 4; jg++)
                ldsm_x4t(bf[2 * jg][0], bf[2 * jg][1],
                         bf[2 * jg + 1][0], bf[2 * jg + 1][1],
                         sB + s * 4096 + btb[jg]);
#pragma unroll
            for (int mt = 0; mt < 4; mt++)
#pragma unroll
                for (int nt = 0; nt < 8; nt++)
                    mma16816(acc[mt][nt], a[mt], bf[nt]);
        }
    }

    // ------------- epilogue: per-row sum of squares -------------
    __shared__ float red[128][2];
#pragma unroll
    for (int mt = 0; mt < 4; mt++) {
        float s0 = 0.0f, s1 = 0.0f;
#pragma unroll
        for (int nt = 0; nt < 8; nt++) {
            s0 = fmaf(acc[mt][nt][0], acc[mt][nt][0], s0);
            s0 = fmaf(acc[mt][nt][1], acc[mt][nt][1], s0);
            s1 = fmaf(acc[mt][nt][2], acc[mt][nt][2], s1);
            s1 = fmaf(acc[mt][nt][3], acc[mt][nt][3], s1);
        }
        s0 += __shfl_xor_sync(0xFFFFFFFF, s0, 1);
        s0 += __shfl_xor_sync(0xFFFFFFFF, s0, 2);
        s1 += __shfl_xor_sync(0xFFFFFFFF, s1, 1);
        s1 += __shfl_xor_sync(0xFFFFFFFF, s1, 2);
        if ((lane & 3) == 0) {
            int r = warp_m * 64 + mt * 16 + (lane >> 2);
            red[r][warp_n] = s0;
            red[r + 8][warp_n] = s1;
        }
    }
    __syncthreads();
    {
        float t = red[tid][0] + red[tid][1];
        g_part[((size_t)dtile * BB + b) * NN + n0 + tid] = t;
    }
}

// ---------------------------------------------------------------------------
// Finalize: out[b] = 0.2 * sum_n sqrt(part0 + part1) + sum_n rowterm
// ---------------------------------------------------------------------------
__global__ __launch_bounds__(256) void finalize_kernel(float* __restrict__ out) {
    int b = blockIdx.x;
    int tid = threadIdx.x;
    float srec = 0.0f, srow = 0.0f;
    for (int n = tid; n < NN; n += 256) {
        float t = g_part[((size_t)0 * BB + b) * NN + n]
                + g_part[((size_t)1 * BB + b) * NN + n];
        srec += sqrtf(t);
        srow += g_rowterm[n];
    }
    __shared__ float s1[256];
    __shared__ float s2[256];
    s1[tid] = srec; s2[tid] = srow;
    __syncthreads();
    for (int s = 128; s > 0; s >>= 1) {
        if (tid < s) { s1[tid] += s1[tid + s]; s2[tid] += s2[tid + s]; }
        __syncthreads();
    }
    if (tid == 0) out[b] = RECONS_LAMDA * s1[0] + s2[0];
}

// ---------------------------------------------------------------------------
extern "C" void kernel_launch(void* const* d_in, const int* in_sizes, int n_in,
                              void* d_out, int out_size) {
    const float* cur = nullptr;
    const float* pre = nullptr;
    const float* rproj = nullptr;
    const float* inc = nullptr;
    int big_seen = 0;
    for (int i = 0; i < n_in; i++) {
        if (in_sizes[i] == DD * DD) rproj = (const float*)d_in[i];
        else if (in_sizes[i] == NN * NN) inc = (const float*)d_in[i];
        else if (in_sizes[i] == BB * NN * DD) {
            if (big_seen == 0) cur = (const float*)d_in[i];
            else pre = (const float*)d_in[i];
            big_seen++;
        }
    }
    float* out = (float*)d_out;

    cudaFuncSetAttribute(gemm_kernel, cudaFuncAttributeMaxDynamicSharedMemorySize, GEMM_SMEM);

    const int n4_big = BB * NN * DD / 4;
    // Launch order keeps gemm_kernel in the ncu capture slot (4th launch).
    conv_inc_kernel<<<NN, 256>>>(inc);                                        // 1
    conv_r_kernel<<<DD * DD / 4 / 256, 256>>>((const float4*)rproj, DD * DD / 4); // 2
    conv_big_kernel<<<dim3(n4_big / 256, 2), 256>>>((const float4*)cur,
                                                    (const float4*)pre, n4_big); // 3
    gemm_kernel<<<dim3(2, 16, BB), 128, GEMM_SMEM>>>();                       // 4
    finalize_kernel<<<BB, 256>>>(out);                                        // 5

    if (out_size >= BB + NN * NN) {
        cudaMemcpyAsync(out + BB, inc, (size_t)NN * NN * sizeof(float),
                        cudaMemcpyDeviceToDevice, 0);
    }
}